// round 3
// baseline (speedup 1.0000x reference)
#include <cuda_runtime.h>

#define B_   256
#define R_   1152
#define C_   10
#define IC_  8
#define OC_  16
#define RT_  16
#define CHUNKS_ (R_/RT_)   /* 72 */

// Scratch (static device memory — no allocations).
__device__ __align__(16) float g_Vsum[B_*C_*OC_];                 // running sum of v_j
__device__ __align__(16) float g_scratch[CHUNKS_*B_*C_*OC_];      // per-r-chunk partial s

// One fused routing pass. Grid: (CHUNKS_, 2), block 256.
// Thread -> (batch pair bp = tid>>2, o-quarter oq = tid&3).
// Each W float4 from smem feeds 8 FMAs (2 batches) -> crossbar bytes/FMA halved.
template<bool FIRST>
__global__ __launch_bounds__(256, 1)
void pass_kernel(const float* __restrict__ x, const float* __restrict__ w) {
    extern __shared__ float4 Ws[];            // [RT_][C_][IC_][4] float4 = 80 KB
    const int tid   = threadIdx.x;
    const int chunk = blockIdx.x;
    const int r0    = chunk * RT_;
    const int oq    = tid & 3;                // which 4-wide quarter of OC
    const int bp    = tid >> 2;               // batch pair 0..63
    const int b0    = blockIdx.y * 128 + bp * 2;

    // Cooperative load of the W tile for RT_ routes (coalesced, float4).
    const float4* wsrc = reinterpret_cast<const float4*>(w) + (size_t)r0 * (C_*IC_*4);
    #pragma unroll
    for (int k = 0; k < (RT_*C_*IC_*4)/256; ++k) Ws[k*256 + tid] = wsrc[k*256 + tid];
    __syncthreads();

    float s0[C_][4], s1[C_][4];
    #pragma unroll
    for (int c = 0; c < C_; ++c)
        #pragma unroll
        for (int j = 0; j < 4; ++j) { s0[c][j] = 0.0f; s1[c][j] = 0.0f; }

    const float* xrow0 = x + ((size_t)b0       * R_ + r0) * IC_;
    const float* xrow1 = x + ((size_t)(b0 + 1) * R_ + r0) * IC_;
    const float* vs0   = g_Vsum +  b0      * (C_*OC_) + oq * 4;
    const float* vs1   = g_Vsum + (b0 + 1) * (C_*OC_) + oq * 4;

    #pragma unroll 1
    for (int r = 0; r < RT_; ++r) {
        float4 xa = *reinterpret_cast<const float4*>(xrow0 + r*IC_);
        float4 xb = *reinterpret_cast<const float4*>(xrow0 + r*IC_ + 4);
        float4 ya = *reinterpret_cast<const float4*>(xrow1 + r*IC_);
        float4 yb = *reinterpret_cast<const float4*>(xrow1 + r*IC_ + 4);
        float xi[8] = {xa.x, xa.y, xa.z, xa.w, xb.x, xb.y, xb.z, xb.w};
        float yi[8] = {ya.x, ya.y, ya.z, ya.w, yb.x, yb.y, yb.z, yb.w};

        const float4* wr = &Ws[(size_t)r * (C_*IC_*4) + oq];

        if (FIRST) {
            // uniform coupling: accumulate u straight into s (no u/t arrays)
            #pragma unroll
            for (int c = 0; c < C_; ++c) {
                #pragma unroll
                for (int i = 0; i < IC_; ++i) {
                    float4 wq = wr[(c*IC_ + i)*4];     // smem broadcast load
                    s0[c][0] += xi[i]*wq.x; s0[c][1] += xi[i]*wq.y;
                    s0[c][2] += xi[i]*wq.z; s0[c][3] += xi[i]*wq.w;
                    s1[c][0] += yi[i]*wq.x; s1[c][1] += yi[i]*wq.y;
                    s1[c][2] += yi[i]*wq.z; s1[c][3] += yi[i]*wq.w;
                }
            }
        } else {
            float u0[C_][4], u1[C_][4];
            float t0[C_], t1[C_];
            #pragma unroll
            for (int c = 0; c < C_; ++c) {
                float a0=0.f,a1=0.f,a2=0.f,a3=0.f;
                float d0=0.f,d1=0.f,d2=0.f,d3=0.f;
                #pragma unroll
                for (int i = 0; i < IC_; ++i) {
                    float4 wq = wr[(c*IC_ + i)*4];
                    a0 += xi[i]*wq.x; a1 += xi[i]*wq.y;
                    a2 += xi[i]*wq.z; a3 += xi[i]*wq.w;
                    d0 += yi[i]*wq.x; d1 += yi[i]*wq.y;
                    d2 += yi[i]*wq.z; d3 += yi[i]*wq.w;
                }
                u0[c][0]=a0; u0[c][1]=a1; u0[c][2]=a2; u0[c][3]=a3;
                u1[c][0]=d0; u1[c][1]=d1; u1[c][2]=d2; u1[c][3]=d3;
                float4 v0 = *reinterpret_cast<const float4*>(vs0 + c*OC_);  // L1-hit
                float4 v1 = *reinterpret_cast<const float4*>(vs1 + c*OC_);
                t0[c] = a0*v0.x + a1*v0.y + a2*v0.z + a3*v0.w;
                t1[c] = d0*v1.x + d1*v1.y + d2*v1.z + d3*v1.w;
            }

            // complete t over the 4 o-quarter lanes (same batch pair)
            #pragma unroll
            for (int c = 0; c < C_; ++c) {
                t0[c] += __shfl_xor_sync(0xffffffffu, t0[c], 1);
                t0[c] += __shfl_xor_sync(0xffffffffu, t0[c], 2);
                t1[c] += __shfl_xor_sync(0xffffffffu, t1[c], 1);
                t1[c] += __shfl_xor_sync(0xffffffffu, t1[c], 2);
            }
            float m0 = t0[0], m1 = t1[0];
            #pragma unroll
            for (int c = 1; c < C_; ++c) { m0 = fmaxf(m0, t0[c]); m1 = fmaxf(m1, t1[c]); }
            float z0 = 0.f, z1 = 0.f;
            #pragma unroll
            for (int c = 0; c < C_; ++c) {
                t0[c] = __expf(t0[c] - m0); z0 += t0[c];
                t1[c] = __expf(t1[c] - m1); z1 += t1[c];
            }
            float inv0 = __fdividef(1.0f, z0);
            float inv1 = __fdividef(1.0f, z1);

            #pragma unroll
            for (int c = 0; c < C_; ++c) {
                float c0 = t0[c] * inv0;
                float c1 = t1[c] * inv1;
                s0[c][0] += c0*u0[c][0]; s0[c][1] += c0*u0[c][1];
                s0[c][2] += c0*u0[c][2]; s0[c][3] += c0*u0[c][3];
                s1[c][0] += c1*u1[c][0]; s1[c][1] += c1*u1[c][1];
                s1[c][2] += c1*u1[c][2]; s1[c][3] += c1*u1[c][3];
            }
        }
    }

    // Write per-chunk partial s (no atomics; reduced in squash kernel).
    float* dst0 = g_scratch + ((size_t)chunk * B_ +  b0     ) * (C_*OC_) + oq * 4;
    float* dst1 = g_scratch + ((size_t)chunk * B_ + (b0 + 1)) * (C_*OC_) + oq * 4;
    const float fscale = FIRST ? 0.1f : 1.0f;
    #pragma unroll
    for (int c = 0; c < C_; ++c) {
        *reinterpret_cast<float4*>(dst0 + c*OC_) =
            make_float4(s0[c][0]*fscale, s0[c][1]*fscale, s0[c][2]*fscale, s0[c][3]*fscale);
        *reinterpret_cast<float4*>(dst1 + c*OC_) =
            make_float4(s1[c][0]*fscale, s1[c][1]*fscale, s1[c][2]*fscale, s1[c][3]*fscale);
    }
}

// Reduce 72 partials, squash, update Vsum (or emit final output).
// Grid: 160 x 256 = 40960 threads, one per (b,c,o). 16-lane groups share (b,c).
template<bool FIRSTV, bool LAST>
__global__ void squash_kernel(float* __restrict__ out) {
    int g = blockIdx.x * 256 + threadIdx.x;
    float s = 0.0f;
    #pragma unroll 8
    for (int k = 0; k < CHUNKS_; ++k) s += g_scratch[(size_t)k * (B_*C_*OC_) + g];
    float sq = s * s;
    #pragma unroll
    for (int m = 8; m >= 1; m >>= 1) sq += __shfl_xor_sync(0xffffffffu, sq, m);
    float n = sqrtf(sq);
    float v = (sq / (1.0f + sq)) * s / (n + 1e-8f);
    if (LAST)        out[g] = v;
    else if (FIRSTV) g_Vsum[g] = v;       // first iteration: overwrite (no init kernel)
    else             g_Vsum[g] += v;
}

extern "C" void kernel_launch(void* const* d_in, const int* in_sizes, int n_in,
                              void* d_out, int out_size) {
    const float* x = (const float*)d_in[0];
    const float* w = (const float*)d_in[1];
    float* out = (float*)d_out;

    const size_t smem = (size_t)RT_ * C_ * IC_ * 4 * sizeof(float4);  // 81920 B
    cudaFuncSetAttribute(pass_kernel<true>,  cudaFuncAttributeMaxDynamicSharedMemorySize, (int)smem);
    cudaFuncSetAttribute(pass_kernel<false>, cudaFuncAttributeMaxDynamicSharedMemorySize, (int)smem);

    dim3 grid(CHUNKS_, 2);

    pass_kernel<true ><<<grid, 256, smem>>>(x, w);    // iter 1 (uniform coupling)
    squash_kernel<true,  false><<<160, 256>>>(out);   // v1, Vsum = v1
    pass_kernel<false><<<grid, 256, smem>>>(x, w);    // iter 2
    squash_kernel<false, false><<<160, 256>>>(out);   // v2, Vsum = v1+v2
    pass_kernel<false><<<grid, 256, smem>>>(x, w);    // iter 3
    squash_kernel<false, true ><<<160, 256>>>(out);   // v3 -> output
}

// round 5
// speedup vs baseline: 1.6255x; 1.6255x over previous
#include <cuda_runtime.h>

#define B_   256
#define R_   1152
#define C_   10
#define IC_  8
#define OC_  16
#define RT_  16
#define CHUNKS_ (R_/RT_)   /* 72 */
#define NG_   (B_*C_*OC_)  /* 40960 */

// Scratch (static device memory — no allocations).
__device__ __align__(16) float g_Vsum[NG_];             // running sum of v_j
__device__ __align__(16) float g_scratch[CHUNKS_*NG_];  // per-r-chunk partial s

// ---------------------------------------------------------------------------
// First routing pass (uniform coupling 0.1): nb=2, osplit=4, ~120 regs.
// Grid (CHUNKS_, 2), block 256. Thread -> (batch pair, o-quarter).
// ---------------------------------------------------------------------------
__global__ __launch_bounds__(256, 1)
void pass_first(const float* __restrict__ x, const float* __restrict__ w) {
    extern __shared__ float4 Ws[];            // [RT_][C_][IC_][4] float4 = 80 KB
    const int tid   = threadIdx.x;
    const int chunk = blockIdx.x;
    const int r0    = chunk * RT_;
    const int oq    = tid & 3;
    const int b0    = blockIdx.y * 128 + (tid >> 2) * 2;

    const float4* wsrc = reinterpret_cast<const float4*>(w) + (size_t)r0 * (C_*IC_*4);
    #pragma unroll
    for (int k = 0; k < (RT_*C_*IC_*4)/256; ++k) Ws[k*256 + tid] = wsrc[k*256 + tid];
    __syncthreads();

    float s0[C_][4], s1[C_][4];
    #pragma unroll
    for (int c = 0; c < C_; ++c)
        #pragma unroll
        for (int j = 0; j < 4; ++j) { s0[c][j] = 0.0f; s1[c][j] = 0.0f; }

    const float* xrow0 = x + ((size_t)b0       * R_ + r0) * IC_;
    const float* xrow1 = x + ((size_t)(b0 + 1) * R_ + r0) * IC_;

    #pragma unroll 1
    for (int r = 0; r < RT_; ++r) {
        float4 xa = *reinterpret_cast<const float4*>(xrow0 + r*IC_);
        float4 xb = *reinterpret_cast<const float4*>(xrow0 + r*IC_ + 4);
        float4 ya = *reinterpret_cast<const float4*>(xrow1 + r*IC_);
        float4 yb = *reinterpret_cast<const float4*>(xrow1 + r*IC_ + 4);
        float xi[8] = {xa.x, xa.y, xa.z, xa.w, xb.x, xb.y, xb.z, xb.w};
        float yi[8] = {ya.x, ya.y, ya.z, ya.w, yb.x, yb.y, yb.z, yb.w};

        const float4* wr = &Ws[(size_t)r * (C_*IC_*4) + oq];
        #pragma unroll
        for (int c = 0; c < C_; ++c) {
            #pragma unroll
            for (int i = 0; i < IC_; ++i) {
                float4 wq = wr[(c*IC_ + i)*4];
                s0[c][0] += xi[i]*wq.x; s0[c][1] += xi[i]*wq.y;
                s0[c][2] += xi[i]*wq.z; s0[c][3] += xi[i]*wq.w;
                s1[c][0] += yi[i]*wq.x; s1[c][1] += yi[i]*wq.y;
                s1[c][2] += yi[i]*wq.z; s1[c][3] += yi[i]*wq.w;
            }
        }
    }

    float* dst0 = g_scratch + ((size_t)chunk * B_ +  b0     ) * (C_*OC_) + oq * 4;
    float* dst1 = g_scratch + ((size_t)chunk * B_ + (b0 + 1)) * (C_*OC_) + oq * 4;
    #pragma unroll
    for (int c = 0; c < C_; ++c) {
        *reinterpret_cast<float4*>(dst0 + c*OC_) =
            make_float4(s0[c][0]*0.1f, s0[c][1]*0.1f, s0[c][2]*0.1f, s0[c][3]*0.1f);
        *reinterpret_cast<float4*>(dst1 + c*OC_) =
            make_float4(s1[c][0]*0.1f, s1[c][1]*0.1f, s1[c][2]*0.1f, s1[c][3]*0.1f);
    }
}

// ---------------------------------------------------------------------------
// Routing iteration pass: nb=1, osplit=2 (round-1 shape, register diet).
// Grid (CHUNKS_, 2), block 256. Thread -> (b = by*128 + tid/2, o-half = tid&1).
// W bytes/FMA = 2; s[10][8] + u[10][8] + t[10] ~= 200 regs target.
// ---------------------------------------------------------------------------
__global__ __launch_bounds__(256, 1)
void pass_iter(const float* __restrict__ x, const float* __restrict__ w) {
    extern __shared__ float4 Ws[];            // 80 KB
    const int tid   = threadIdx.x;
    const int chunk = blockIdx.x;
    const int r0    = chunk * RT_;
    const int oh    = tid & 1;
    const int b     = blockIdx.y * 128 + (tid >> 1);

    const float4* wsrc = reinterpret_cast<const float4*>(w) + (size_t)r0 * (C_*IC_*4);
    #pragma unroll
    for (int k = 0; k < (RT_*C_*IC_*4)/256; ++k) Ws[k*256 + tid] = wsrc[k*256 + tid];
    __syncthreads();

    float s[C_][8];
    #pragma unroll
    for (int c = 0; c < C_; ++c)
        #pragma unroll
        for (int j = 0; j < 8; ++j) s[c][j] = 0.0f;

    const float* xrow = x + ((size_t)b * R_ + r0) * IC_;
    const float* vsum = g_Vsum + b * (C_*OC_) + oh * 8;

    #pragma unroll 1
    for (int r = 0; r < RT_; ++r) {
        float4 xa = *reinterpret_cast<const float4*>(xrow + r*IC_);
        float4 xb = *reinterpret_cast<const float4*>(xrow + r*IC_ + 4);
        float xi[8] = {xa.x, xa.y, xa.z, xa.w, xb.x, xb.y, xb.z, xb.w};

        const float4* wr = &Ws[(size_t)r * (C_*IC_*4) + oh*2];

        float u[C_][8];
        float t[C_];
        #pragma unroll
        for (int c = 0; c < C_; ++c) {
            float a0=0.f,a1=0.f,a2=0.f,a3=0.f,a4=0.f,a5=0.f,a6=0.f,a7=0.f;
            #pragma unroll
            for (int i = 0; i < IC_; ++i) {
                float4 wA = wr[(c*IC_ + i)*4];
                float4 wB = wr[(c*IC_ + i)*4 + 1];
                a0 += xi[i]*wA.x; a1 += xi[i]*wA.y;
                a2 += xi[i]*wA.z; a3 += xi[i]*wA.w;
                a4 += xi[i]*wB.x; a5 += xi[i]*wB.y;
                a6 += xi[i]*wB.z; a7 += xi[i]*wB.w;
            }
            u[c][0]=a0; u[c][1]=a1; u[c][2]=a2; u[c][3]=a3;
            u[c][4]=a4; u[c][5]=a5; u[c][6]=a6; u[c][7]=a7;
            float4 vA = *reinterpret_cast<const float4*>(vsum + c*OC_);      // L1-hit
            float4 vB = *reinterpret_cast<const float4*>(vsum + c*OC_ + 4);
            t[c] = a0*vA.x + a1*vA.y + a2*vA.z + a3*vA.w
                 + a4*vB.x + a5*vB.y + a6*vB.z + a7*vB.w;
        }

        // partner lane (same b, other o-half) completes the dot product
        #pragma unroll
        for (int c = 0; c < C_; ++c) t[c] += __shfl_xor_sync(0xffffffffu, t[c], 1);
        float m = t[0];
        #pragma unroll
        for (int c = 1; c < C_; ++c) m = fmaxf(m, t[c]);
        float z = 0.0f;
        #pragma unroll
        for (int c = 0; c < C_; ++c) { t[c] = __expf(t[c] - m); z += t[c]; }
        float inv = __fdividef(1.0f, z);

        #pragma unroll
        for (int c = 0; c < C_; ++c) {
            float cc = t[c] * inv;
            #pragma unroll
            for (int j = 0; j < 8; ++j) s[c][j] += cc * u[c][j];
        }
    }

    float* dst = g_scratch + ((size_t)chunk * B_ + b) * (C_*OC_) + oh * 8;
    #pragma unroll
    for (int c = 0; c < C_; ++c) {
        *reinterpret_cast<float4*>(dst + c*OC_) =
            make_float4(s[c][0], s[c][1], s[c][2], s[c][3]);
        *reinterpret_cast<float4*>(dst + c*OC_ + 4) =
            make_float4(s[c][4], s[c][5], s[c][6], s[c][7]);
    }
}

// ---------------------------------------------------------------------------
// Reduce 72 partials, squash, update Vsum / emit output.
// Block 1024 = 256 g x 4 k-quarters (18 independent coalesced loads each),
// smem combine, then 16-lane shfl squash on the first 256 threads.
// Grid 160.
// ---------------------------------------------------------------------------
template<bool FIRSTV, bool LAST>
__global__ __launch_bounds__(1024, 2)
void squash_kernel(float* __restrict__ out) {
    const int tid = threadIdx.x;
    const int ks  = tid >> 8;          // 0..3
    const int gl  = tid & 255;
    const int g   = blockIdx.x * 256 + gl;

    float s = 0.0f;
    #pragma unroll
    for (int k = 0; k < CHUNKS_/4; ++k)
        s += g_scratch[(size_t)(ks * (CHUNKS_/4) + k) * NG_ + g];

    __shared__ float red[4][256];
    red[ks][gl] = s;
    __syncthreads();

    if (tid < 256) {
        s = red[0][gl] + red[1][gl] + red[2][gl] + red[3][gl];
        float sq = s * s;
        #pragma unroll
        for (int m = 8; m >= 1; m >>= 1) sq += __shfl_xor_sync(0xffffffffu, sq, m);
        float n = sqrtf(sq);
        float v = (sq / (1.0f + sq)) * s / (n + 1e-8f);
        if (LAST)        out[g] = v;
        else if (FIRSTV) g_Vsum[g] = v;
        else             g_Vsum[g] += v;
    }
}

extern "C" void kernel_launch(void* const* d_in, const int* in_sizes, int n_in,
                              void* d_out, int out_size) {
    const float* x = (const float*)d_in[0];
    const float* w = (const float*)d_in[1];
    float* out = (float*)d_out;

    const size_t smem = (size_t)RT_ * C_ * IC_ * 4 * sizeof(float4);  // 81920 B
    cudaFuncSetAttribute(pass_first, cudaFuncAttributeMaxDynamicSharedMemorySize, (int)smem);
    cudaFuncSetAttribute(pass_iter,  cudaFuncAttributeMaxDynamicSharedMemorySize, (int)smem);

    dim3 grid(CHUNKS_, 2);

    pass_first<<<grid, 256, smem>>>(x, w);            // iter 1 (uniform coupling)
    squash_kernel<true,  false><<<160, 1024>>>(out);  // v1, Vsum = v1
    pass_iter<<<grid, 256, smem>>>(x, w);             // iter 2
    squash_kernel<false, false><<<160, 1024>>>(out);  // v2, Vsum = v1+v2
    pass_iter<<<grid, 256, smem>>>(x, w);             // iter 3
    squash_kernel<false, true ><<<160, 1024>>>(out);  // v3 -> output
}